// round 3
// baseline (speedup 1.0000x reference)
#include <cuda_runtime.h>
#include <math.h>

#define EMB   128
#define NSP   95
#define NRBF  16
#define EPW   4

// ---------------- device-global scratch (no allocations allowed) ----------------
__device__ float g_Wc[NRBF * EMB];        // W_rbf @ W_scalar[256:384]
__device__ float g_bias[EMB];             // b_scalar + b_rbf @ W_scalar[256:384]
__device__ float g_T1[NSP * EMB];         // emb @ W_scalar[0:128]
__device__ float g_T2[NSP * EMB];         // emb @ W_scalar[128:256]
__device__ float g_U1[NSP * 3 * EMB];     // U1[z,d,m] = sum_k vemb[z,k,d] * Wv[k,m]
__device__ float g_U2[NSP * 3 * EMB];
__device__ float g_Vs1[NSP * 6 * EMB];    // symmetrized V tables, layout [z][pair][m]
__device__ float g_Vs2[NSP * 6 * EMB];
__device__ float g_C[3 * EMB];            // C[d',m] = sum_k b_vector[k] * W_v2s[3k+d',m]
__device__ float g_S1[NSP * 3];           // row sums of U1 (over m)
__device__ float g_S2[NSP * 3];
__device__ float g_sb;                    // sum(b_vector)

// ---------------- precompute kernel 1: scalar-branch tables ----------------
__global__ void pre_scalar(const float* __restrict__ W_rbf,
                           const float* __restrict__ b_rbf,
                           const float* __restrict__ W_scalar,
                           const float* __restrict__ b_scalar,
                           const float* __restrict__ emb) {
    int m = threadIdx.x;      // 0..127
    int b = blockIdx.x;
    if (b < NRBF) {
        float s = 0.f;
        #pragma unroll 4
        for (int c = 0; c < EMB; c++)
            s = fmaf(W_rbf[b * EMB + c], W_scalar[(2 * EMB + c) * EMB + m], s);
        g_Wc[b * EMB + m] = s;
    } else if (b == NRBF) {
        float s = b_scalar[m];
        #pragma unroll 4
        for (int c = 0; c < EMB; c++)
            s = fmaf(b_rbf[c], W_scalar[(2 * EMB + c) * EMB + m], s);
        g_bias[m] = s;
    } else {
        int z = b - NRBF - 1; // 0..94
        float s1 = 0.f, s2 = 0.f;
        #pragma unroll 4
        for (int k = 0; k < EMB; k++) {
            float e = emb[z * EMB + k];
            s1 = fmaf(e, W_scalar[k * EMB + m], s1);
            s2 = fmaf(e, W_scalar[(EMB + k) * EMB + m], s2);
        }
        g_T1[z * EMB + m] = s1;
        g_T2[z * EMB + m] = s2;
    }
}

// ---------------- precompute kernel 2: U tables, S sums, C, sb ----------------
__global__ void pre_vec(const float* __restrict__ vemb,
                        const float* __restrict__ W_vector,
                        const float* __restrict__ b_vector,
                        const float* __restrict__ W_v2s) {
    __shared__ float sh[128];
    int m = threadIdx.x;
    int b = blockIdx.x;
    if (b < NSP * 3) {
        int z = b / 3, d = b % 3;
        float u1 = 0.f, u2 = 0.f;
        #pragma unroll 4
        for (int k = 0; k < EMB; k++) {
            float v = vemb[(z * EMB + k) * 3 + d];
            u1 = fmaf(v, W_vector[k * EMB + m], u1);
            u2 = fmaf(v, W_vector[(EMB + k) * EMB + m], u2);
        }
        g_U1[(z * 3 + d) * EMB + m] = u1;
        g_U2[(z * 3 + d) * EMB + m] = u2;
        sh[m] = u1; __syncthreads();
        for (int s = 64; s > 0; s >>= 1) { if (m < s) sh[m] += sh[m + s]; __syncthreads(); }
        if (m == 0) g_S1[z * 3 + d] = sh[0];
        __syncthreads();
        sh[m] = u2; __syncthreads();
        for (int s = 64; s > 0; s >>= 1) { if (m < s) sh[m] += sh[m + s]; __syncthreads(); }
        if (m == 0) g_S2[z * 3 + d] = sh[0];
    } else {
        int dp = b - NSP * 3; // 0..2
        float s = 0.f;
        #pragma unroll 4
        for (int k = 0; k < EMB; k++)
            s = fmaf(b_vector[k], W_v2s[(k * 3 + dp) * EMB + m], s);
        g_C[dp * EMB + m] = s;
        if (dp == 0) {
            sh[m] = b_vector[m]; __syncthreads();
            for (int s2 = 64; s2 > 0; s2 >>= 1) { if (m < s2) sh[m] += sh[m + s2]; __syncthreads(); }
            if (m == 0) g_sb = sh[0];
        }
    }
}

// ---------------- precompute kernel 3: symmetrized V tables, [z][pair] layout ----------------
__global__ void pre_V(const float* __restrict__ W_v2s) {
    int m = threadIdx.x;
    int b = blockIdx.x;  // 0..569
    int p = b / NSP, z = b % NSP;
    const int PD[6]  = {0, 1, 2, 0, 0, 1};
    const int PDP[6] = {0, 1, 2, 1, 2, 2};
    int d = PD[p], dp = PDP[p];
    float v1 = 0.f, v2 = 0.f;
    #pragma unroll 4
    for (int k = 0; k < EMB; k++) {
        float w = W_v2s[(k * 3 + dp) * EMB + m];
        v1 = fmaf(g_U1[(z * 3 + d) * EMB + k], w, v1);
        v2 = fmaf(g_U2[(z * 3 + d) * EMB + k], w, v2);
    }
    if (d != dp) {
        #pragma unroll 4
        for (int k = 0; k < EMB; k++) {
            float w = W_v2s[(k * 3 + d) * EMB + m];
            v1 = fmaf(g_U1[(z * 3 + dp) * EMB + k], w, v1);
            v2 = fmaf(g_U2[(z * 3 + dp) * EMB + k], w, v2);
        }
    }
    g_Vs1[(z * 6 + p) * EMB + m] = v1;
    g_Vs2[(z * 6 + p) * EMB + m] = v2;
}

// ---------------- main edge kernel ----------------
__global__ __launch_bounds__(256, 4)
void edge_kernel(const float* __restrict__ rbf,
                 const int* __restrict__ idnb_i,
                 const int* __restrict__ idnb_j,
                 const float* __restrict__ R,
                 const int* __restrict__ Z,
                 float* __restrict__ out,
                 int E) {
    __shared__ float s_Wc[NRBF * EMB];   // 8 KB
    __shared__ float s_bias[EMB];
    __shared__ float s_C[3 * EMB];
    __shared__ float s_S1[NSP * 3];
    __shared__ float s_S2[NSP * 3];
    __shared__ float s_sb;

    for (int i = threadIdx.x; i < NRBF * EMB; i += 256) s_Wc[i] = g_Wc[i];
    for (int i = threadIdx.x; i < EMB; i += 256)        s_bias[i] = g_bias[i];
    for (int i = threadIdx.x; i < 3 * EMB; i += 256)    s_C[i] = g_C[i];
    for (int i = threadIdx.x; i < NSP * 3; i += 256) { s_S1[i] = g_S1[i]; s_S2[i] = g_S2[i]; }
    if (threadIdx.x == 0) s_sb = g_sb;
    __syncthreads();

    const int lane  = threadIdx.x & 31;
    const int warp  = blockIdx.x * (blockDim.x >> 5) + (threadIdx.x >> 5);
    const int nwarp = gridDim.x * (blockDim.x >> 5);
    const int ntiles = (E + EPW - 1) / EPW;
    const size_t o2 = (size_t)E * EMB;

    const float4* __restrict__ T1f  = reinterpret_cast<const float4*>(g_T1);
    const float4* __restrict__ T2f  = reinterpret_cast<const float4*>(g_T2);
    const float4* __restrict__ V1f  = reinterpret_cast<const float4*>(g_Vs1);
    const float4* __restrict__ V2f  = reinterpret_cast<const float4*>(g_Vs2);
    const float4* __restrict__ Wcf  = reinterpret_cast<const float4*>(s_Wc);
    const float4* __restrict__ Cf   = reinterpret_cast<const float4*>(s_C);
    const float4* __restrict__ Bf   = reinterpret_cast<const float4*>(s_bias);

    for (int t = warp; t < ntiles; t += nwarp) {
        int base = t * EPW;
        float4 acc[EPW];
        float bdx[EPW], bdy[EPW], bdz[EPW];
        int zi[EPW], zj[EPW];

        #pragma unroll
        for (int e = 0; e < EPW; e++) {
            int edge = base + e;
            if (edge >= E) edge = E - 1;
            int i = idnb_i[edge];
            int j = idnb_j[edge];
            zi[e] = Z[i];
            zj[e] = Z[j];
            float bx = R[j * 3 + 0] - R[i * 3 + 0];
            float by = R[j * 3 + 1] - R[i * 3 + 1];
            float bz = R[j * 3 + 2] - R[i * 3 + 2];
            float n = sqrtf(bx * bx + by * by + bz * bz) + 1e-8f;
            float inv = 1.0f / n;
            bdx[e] = bx * inv; bdy[e] = by * inv; bdz[e] = bz * inv;

            // scalar branch: bias + rbf @ Wc
            float rv = rbf[edge * NRBF + (lane & 15)];
            float4 a = Bf[lane];
            #pragma unroll
            for (int r = 0; r < NRBF; r++) {
                float c = __shfl_sync(0xffffffffu, rv, r);
                float4 w = Wcf[r * 32 + lane];
                a.x = fmaf(c, w.x, a.x);
                a.y = fmaf(c, w.y, a.y);
                a.z = fmaf(c, w.z, a.z);
                a.w = fmaf(c, w.w, a.w);
            }
            // species-table gathers
            float4 t1 = T1f[zi[e] * 32 + lane];
            float4 t2 = T2f[zj[e] * 32 + lane];
            a.x += t1.x + t2.x; a.y += t1.y + t2.y;
            a.z += t1.z + t2.z; a.w += t1.w + t2.w;
            // bias-of-vector term: sum_d' bd_d' * C[d',m]
            float4 c0 = Cf[lane], c1 = Cf[32 + lane], c2 = Cf[64 + lane];
            a.x += bdx[e] * c0.x + bdy[e] * c1.x + bdz[e] * c2.x;
            a.y += bdx[e] * c0.y + bdy[e] * c1.y + bdz[e] * c2.y;
            a.z += bdx[e] * c0.z + bdy[e] * c1.z + bdz[e] * c2.z;
            a.w += bdx[e] * c0.w + bdy[e] * c1.w + bdz[e] * c2.w;
            acc[e] = a;

            // x_vec_final = bd * sum_k x_vec[k]
            float sx = bdx[e] * (s_S1[zi[e] * 3 + 0] + s_S2[zj[e] * 3 + 0])
                     + bdy[e] * (s_S1[zi[e] * 3 + 1] + s_S2[zj[e] * 3 + 1])
                     + bdz[e] * (s_S1[zi[e] * 3 + 2] + s_S2[zj[e] * 3 + 2])
                     + s_sb;
            if (lane == 0) {
                out[o2 + (size_t)edge * 3 + 0] = bdx[e] * sx;
                out[o2 + (size_t)edge * 3 + 1] = bdy[e] * sx;
                out[o2 + (size_t)edge * 3 + 2] = bdz[e] * sx;
            }
        }

        // quadratic-form pair loop: vec_scalar contribution ([z][pair] layout)
        const int PD[6]  = {0, 1, 2, 0, 0, 1};
        const int PDP[6] = {0, 1, 2, 1, 2, 2};
        #pragma unroll
        for (int p = 0; p < 6; p++) {
            const int d = PD[p], dp = PDP[p];
            #pragma unroll
            for (int e = 0; e < EPW; e++) {
                float b1 = (d  == 0) ? bdx[e] : (d  == 1) ? bdy[e] : bdz[e];
                float b2 = (dp == 0) ? bdx[e] : (dp == 1) ? bdy[e] : bdz[e];
                float c = b1 * b2;
                float4 v1 = V1f[(zi[e] * 6 + p) * 32 + lane];
                float4 v2 = V2f[(zj[e] * 6 + p) * 32 + lane];
                acc[e].x = fmaf(c, v1.x + v2.x, acc[e].x);
                acc[e].y = fmaf(c, v1.y + v2.y, acc[e].y);
                acc[e].z = fmaf(c, v1.z + v2.z, acc[e].z);
                acc[e].w = fmaf(c, v1.w + v2.w, acc[e].w);
            }
        }

        #pragma unroll
        for (int e = 0; e < EPW; e++) {
            int edge = base + e;
            if (edge >= E) edge = E - 1;
            reinterpret_cast<float4*>(out + (size_t)edge * EMB)[lane] = acc[e];
        }
    }
}

// ---------------- launcher ----------------
extern "C" void kernel_launch(void* const* d_in, const int* in_sizes, int n_in,
                              void* d_out, int out_size) {
    const int*   Z        = (const int*)d_in[0];
    const float* rbf      = (const float*)d_in[1];
    const int*   idnb_i   = (const int*)d_in[2];
    const int*   idnb_j   = (const int*)d_in[3];
    const float* R        = (const float*)d_in[4];
    const float* emb      = (const float*)d_in[5];
    const float* vemb     = (const float*)d_in[6];
    const float* W_rbf    = (const float*)d_in[7];
    const float* b_rbf    = (const float*)d_in[8];
    const float* W_scalar = (const float*)d_in[9];
    const float* b_scalar = (const float*)d_in[10];
    const float* W_vector = (const float*)d_in[11];
    const float* b_vector = (const float*)d_in[12];
    const float* W_v2s    = (const float*)d_in[13];
    int E = in_sizes[2];

    pre_scalar<<<NRBF + 1 + NSP, 128>>>(W_rbf, b_rbf, W_scalar, b_scalar, emb);
    pre_vec<<<NSP * 3 + 3, 128>>>(vemb, W_vector, b_vector, W_v2s);
    pre_V<<<6 * NSP, 128>>>(W_v2s);
    edge_kernel<<<2048, 256>>>(rbf, idnb_i, idnb_j, R, Z, (float*)d_out, E);
}

// round 4
// speedup vs baseline: 1.9638x; 1.9638x over previous
#include <cuda_runtime.h>
#include <cuda_fp16.h>
#include <math.h>

#define EMB   128
#define NSP   95
#define NRBF  16
#define EPW   4

// ---------------- device-global scratch (no allocations allowed) ----------------
__device__ float g_Wc[NRBF * EMB];        // W_rbf @ W_scalar[256:384]
__device__ float g_bias[EMB];             // b_scalar + b_rbf @ W_scalar[256:384]
__device__ float g_T1[NSP * EMB];         // emb @ W_scalar[0:128]
__device__ float g_T2[NSP * EMB];         // emb @ W_scalar[128:256]
__device__ float g_U1[NSP * 3 * EMB];     // U1[z,d,m] = sum_k vemb[z,k,d] * Wv[k,m]
__device__ float g_U2[NSP * 3 * EMB];
__device__ __half g_Vh1[NSP * 6 * EMB];   // symmetrized V tables, fp16, layout [z][pair][m]
__device__ __half g_Vh2[NSP * 6 * EMB];
__device__ float g_C[3 * EMB];            // C[d',m] = sum_k b_vector[k] * W_v2s[3k+d',m]
__device__ float g_S1[NSP * 3];           // row sums of U1 (over m)
__device__ float g_S2[NSP * 3];
__device__ float g_sb;                    // sum(b_vector)

// ---------------- precompute kernel 1: scalar-branch tables ----------------
__global__ void pre_scalar(const float* __restrict__ W_rbf,
                           const float* __restrict__ b_rbf,
                           const float* __restrict__ W_scalar,
                           const float* __restrict__ b_scalar,
                           const float* __restrict__ emb) {
    int m = threadIdx.x;      // 0..127
    int b = blockIdx.x;
    if (b < NRBF) {
        float s = 0.f;
        #pragma unroll 4
        for (int c = 0; c < EMB; c++)
            s = fmaf(W_rbf[b * EMB + c], W_scalar[(2 * EMB + c) * EMB + m], s);
        g_Wc[b * EMB + m] = s;
    } else if (b == NRBF) {
        float s = b_scalar[m];
        #pragma unroll 4
        for (int c = 0; c < EMB; c++)
            s = fmaf(b_rbf[c], W_scalar[(2 * EMB + c) * EMB + m], s);
        g_bias[m] = s;
    } else {
        int z = b - NRBF - 1; // 0..94
        float s1 = 0.f, s2 = 0.f;
        #pragma unroll 4
        for (int k = 0; k < EMB; k++) {
            float e = emb[z * EMB + k];
            s1 = fmaf(e, W_scalar[k * EMB + m], s1);
            s2 = fmaf(e, W_scalar[(EMB + k) * EMB + m], s2);
        }
        g_T1[z * EMB + m] = s1;
        g_T2[z * EMB + m] = s2;
    }
}

// ---------------- precompute kernel 2: U tables, S sums, C, sb ----------------
__global__ void pre_vec(const float* __restrict__ vemb,
                        const float* __restrict__ W_vector,
                        const float* __restrict__ b_vector,
                        const float* __restrict__ W_v2s) {
    __shared__ float sh[128];
    int m = threadIdx.x;
    int b = blockIdx.x;
    if (b < NSP * 3) {
        int z = b / 3, d = b % 3;
        float u1 = 0.f, u2 = 0.f;
        #pragma unroll 4
        for (int k = 0; k < EMB; k++) {
            float v = vemb[(z * EMB + k) * 3 + d];
            u1 = fmaf(v, W_vector[k * EMB + m], u1);
            u2 = fmaf(v, W_vector[(EMB + k) * EMB + m], u2);
        }
        g_U1[(z * 3 + d) * EMB + m] = u1;
        g_U2[(z * 3 + d) * EMB + m] = u2;
        sh[m] = u1; __syncthreads();
        for (int s = 64; s > 0; s >>= 1) { if (m < s) sh[m] += sh[m + s]; __syncthreads(); }
        if (m == 0) g_S1[z * 3 + d] = sh[0];
        __syncthreads();
        sh[m] = u2; __syncthreads();
        for (int s = 64; s > 0; s >>= 1) { if (m < s) sh[m] += sh[m + s]; __syncthreads(); }
        if (m == 0) g_S2[z * 3 + d] = sh[0];
    } else {
        int dp = b - NSP * 3; // 0..2
        float s = 0.f;
        #pragma unroll 4
        for (int k = 0; k < EMB; k++)
            s = fmaf(b_vector[k], W_v2s[(k * 3 + dp) * EMB + m], s);
        g_C[dp * EMB + m] = s;
        if (dp == 0) {
            sh[m] = b_vector[m]; __syncthreads();
            for (int s2 = 64; s2 > 0; s2 >>= 1) { if (m < s2) sh[m] += sh[m + s2]; __syncthreads(); }
            if (m == 0) g_sb = sh[0];
        }
    }
}

// ---------------- precompute kernel 3: symmetrized V tables (fp16, [z][pair]) ----------------
__global__ void pre_V(const float* __restrict__ W_v2s) {
    int m = threadIdx.x;
    int b = blockIdx.x;  // 0..569
    int p = b / NSP, z = b % NSP;
    const int PD[6]  = {0, 1, 2, 0, 0, 1};
    const int PDP[6] = {0, 1, 2, 1, 2, 2};
    int d = PD[p], dp = PDP[p];
    float v1 = 0.f, v2 = 0.f;
    #pragma unroll 4
    for (int k = 0; k < EMB; k++) {
        float w = W_v2s[(k * 3 + dp) * EMB + m];
        v1 = fmaf(g_U1[(z * 3 + d) * EMB + k], w, v1);
        v2 = fmaf(g_U2[(z * 3 + d) * EMB + k], w, v2);
    }
    if (d != dp) {
        #pragma unroll 4
        for (int k = 0; k < EMB; k++) {
            float w = W_v2s[(k * 3 + d) * EMB + m];
            v1 = fmaf(g_U1[(z * 3 + dp) * EMB + k], w, v1);
            v2 = fmaf(g_U2[(z * 3 + dp) * EMB + k], w, v2);
        }
    }
    g_Vh1[(z * 6 + p) * EMB + m] = __float2half(v1);
    g_Vh2[(z * 6 + p) * EMB + m] = __float2half(v2);
}

// ---------------- main edge kernel ----------------
__global__ __launch_bounds__(256, 3)
void edge_kernel(const float* __restrict__ rbf,
                 const int* __restrict__ idnb_i,
                 const int* __restrict__ idnb_j,
                 const float* __restrict__ R,
                 const int* __restrict__ Z,
                 float* __restrict__ out,
                 int E) {
    __shared__ float s_Wc[NRBF * EMB];   // 8 KB
    __shared__ float s_bias[EMB];
    __shared__ float s_C[3 * EMB];
    __shared__ float s_S1[NSP * 3];
    __shared__ float s_S2[NSP * 3];
    __shared__ float s_sb;

    for (int i = threadIdx.x; i < NRBF * EMB; i += 256) s_Wc[i] = g_Wc[i];
    for (int i = threadIdx.x; i < EMB; i += 256)        s_bias[i] = g_bias[i];
    for (int i = threadIdx.x; i < 3 * EMB; i += 256)    s_C[i] = g_C[i];
    for (int i = threadIdx.x; i < NSP * 3; i += 256) { s_S1[i] = g_S1[i]; s_S2[i] = g_S2[i]; }
    if (threadIdx.x == 0) s_sb = g_sb;
    __syncthreads();

    const int lane  = threadIdx.x & 31;
    const int warp  = blockIdx.x * (blockDim.x >> 5) + (threadIdx.x >> 5);
    const int nwarp = gridDim.x * (blockDim.x >> 5);
    const int ntiles = (E + EPW - 1) / EPW;
    const size_t o2 = (size_t)E * EMB;

    const float4* __restrict__ T1f = reinterpret_cast<const float4*>(g_T1);
    const float4* __restrict__ T2f = reinterpret_cast<const float4*>(g_T2);
    const uint2*  __restrict__ V1h = reinterpret_cast<const uint2*>(g_Vh1);
    const uint2*  __restrict__ V2h = reinterpret_cast<const uint2*>(g_Vh2);
    const float4* __restrict__ Wcf = reinterpret_cast<const float4*>(s_Wc);
    const float4* __restrict__ Cf  = reinterpret_cast<const float4*>(s_C);
    const float4* __restrict__ Bf  = reinterpret_cast<const float4*>(s_bias);

    for (int t = warp; t < ntiles; t += nwarp) {
        int base = t * EPW;
        float4 acc[EPW];
        float bdx[EPW], bdy[EPW], bdz[EPW];
        int zi[EPW], zj[EPW];
        float rv[EPW];

        // ---- per-edge meta: indices, bond dirs, rbf row, vector output ----
        #pragma unroll
        for (int e = 0; e < EPW; e++) {
            int edge = base + e;
            if (edge >= E) edge = E - 1;
            int i = idnb_i[edge];
            int j = idnb_j[edge];
            zi[e] = Z[i];
            zj[e] = Z[j];
            float bx = R[j * 3 + 0] - R[i * 3 + 0];
            float by = R[j * 3 + 1] - R[i * 3 + 1];
            float bz = R[j * 3 + 2] - R[i * 3 + 2];
            float n = sqrtf(bx * bx + by * by + bz * bz) + 1e-8f;
            float inv = 1.0f / n;
            bdx[e] = bx * inv; bdy[e] = by * inv; bdz[e] = bz * inv;
            rv[e] = rbf[edge * NRBF + (lane & 15)];

            float sx = bdx[e] * (s_S1[zi[e] * 3 + 0] + s_S2[zj[e] * 3 + 0])
                     + bdy[e] * (s_S1[zi[e] * 3 + 1] + s_S2[zj[e] * 3 + 1])
                     + bdz[e] * (s_S1[zi[e] * 3 + 2] + s_S2[zj[e] * 3 + 2])
                     + s_sb;
            if (lane == 0) {
                out[o2 + (size_t)edge * 3 + 0] = bdx[e] * sx;
                out[o2 + (size_t)edge * 3 + 1] = bdy[e] * sx;
                out[o2 + (size_t)edge * 3 + 2] = bdz[e] * sx;
            }
        }

        // ---- acc init: bias + species tables ----
        {
            float4 b0 = Bf[lane];
            #pragma unroll
            for (int e = 0; e < EPW; e++) {
                float4 t1 = T1f[zi[e] * 32 + lane];
                float4 t2 = T2f[zj[e] * 32 + lane];
                acc[e].x = b0.x + t1.x + t2.x;
                acc[e].y = b0.y + t1.y + t2.y;
                acc[e].z = b0.z + t1.z + t2.z;
                acc[e].w = b0.w + t1.w + t2.w;
            }
        }

        // ---- rbf @ Wc, Wc row hoisted across edges (1 LDS per r) ----
        #pragma unroll
        for (int r = 0; r < NRBF; r++) {
            float4 w = Wcf[r * 32 + lane];
            #pragma unroll
            for (int e = 0; e < EPW; e++) {
                float c = __shfl_sync(0xffffffffu, rv[e], r);
                acc[e].x = fmaf(c, w.x, acc[e].x);
                acc[e].y = fmaf(c, w.y, acc[e].y);
                acc[e].z = fmaf(c, w.z, acc[e].z);
                acc[e].w = fmaf(c, w.w, acc[e].w);
            }
        }

        // ---- bias-of-vector term, C rows hoisted ----
        {
            float4 c0 = Cf[lane], c1 = Cf[32 + lane], c2 = Cf[64 + lane];
            #pragma unroll
            for (int e = 0; e < EPW; e++) {
                acc[e].x += bdx[e] * c0.x + bdy[e] * c1.x + bdz[e] * c2.x;
                acc[e].y += bdx[e] * c0.y + bdy[e] * c1.y + bdz[e] * c2.y;
                acc[e].z += bdx[e] * c0.z + bdy[e] * c1.z + bdz[e] * c2.z;
                acc[e].w += bdx[e] * c0.w + bdy[e] * c1.w + bdz[e] * c2.w;
            }
        }

        // ---- quadratic-form pair loop (fp16 tables, [z][pair] layout) ----
        const int PD[6]  = {0, 1, 2, 0, 0, 1};
        const int PDP[6] = {0, 1, 2, 1, 2, 2};
        #pragma unroll
        for (int p = 0; p < 6; p++) {
            const int d = PD[p], dp = PDP[p];
            #pragma unroll
            for (int e = 0; e < EPW; e++) {
                float b1 = (d  == 0) ? bdx[e] : (d  == 1) ? bdy[e] : bdz[e];
                float b2 = (dp == 0) ? bdx[e] : (dp == 1) ? bdy[e] : bdz[e];
                float c = b1 * b2;
                uint2 r1 = V1h[(zi[e] * 6 + p) * 32 + lane];
                uint2 r2 = V2h[(zj[e] * 6 + p) * 32 + lane];
                float2 a0 = __half22float2(*reinterpret_cast<__half2*>(&r1.x));
                float2 a1 = __half22float2(*reinterpret_cast<__half2*>(&r1.y));
                float2 b0 = __half22float2(*reinterpret_cast<__half2*>(&r2.x));
                float2 b1v = __half22float2(*reinterpret_cast<__half2*>(&r2.y));
                acc[e].x = fmaf(c, a0.x + b0.x, acc[e].x);
                acc[e].y = fmaf(c, a0.y + b0.y, acc[e].y);
                acc[e].z = fmaf(c, a1.x + b1v.x, acc[e].z);
                acc[e].w = fmaf(c, a1.y + b1v.y, acc[e].w);
            }
        }

        // ---- store scalar block ----
        #pragma unroll
        for (int e = 0; e < EPW; e++) {
            int edge = base + e;
            if (edge >= E) edge = E - 1;
            reinterpret_cast<float4*>(out + (size_t)edge * EMB)[lane] = acc[e];
        }
    }
}

// ---------------- launcher ----------------
extern "C" void kernel_launch(void* const* d_in, const int* in_sizes, int n_in,
                              void* d_out, int out_size) {
    const int*   Z        = (const int*)d_in[0];
    const float* rbf      = (const float*)d_in[1];
    const int*   idnb_i   = (const int*)d_in[2];
    const int*   idnb_j   = (const int*)d_in[3];
    const float* R        = (const float*)d_in[4];
    const float* emb      = (const float*)d_in[5];
    const float* vemb     = (const float*)d_in[6];
    const float* W_rbf    = (const float*)d_in[7];
    const float* b_rbf    = (const float*)d_in[8];
    const float* W_scalar = (const float*)d_in[9];
    const float* b_scalar = (const float*)d_in[10];
    const float* W_vector = (const float*)d_in[11];
    const float* b_vector = (const float*)d_in[12];
    const float* W_v2s    = (const float*)d_in[13];
    int E = in_sizes[2];

    pre_scalar<<<NRBF + 1 + NSP, 128>>>(W_rbf, b_rbf, W_scalar, b_scalar, emb);
    pre_vec<<<NSP * 3 + 3, 128>>>(vemb, W_vector, b_vector, W_v2s);
    pre_V<<<6 * NSP, 128>>>(W_v2s);
    edge_kernel<<<2048, 256>>>(rbf, idnb_i, idnb_j, R, Z, (float*)d_out, E);
}

// round 7
// speedup vs baseline: 2.5349x; 1.2908x over previous
#include <cuda_runtime.h>
#include <cuda_fp16.h>
#include <math.h>

#define EMB   128
#define NSP   95
#define NPAIR (NSP * NSP)
#define NRBF  16
#define EPW   4

// ---------------- device-global scratch ----------------
__device__ float g_Wc[NRBF * EMB];
__device__ float g_bias[EMB];
__device__ float g_T1[NSP * EMB];
__device__ float g_T2[NSP * EMB];
__device__ float g_U1[NSP * 3 * EMB];
__device__ float g_U2[NSP * 3 * EMB];
__device__ float g_Vs1[NSP * 6 * EMB];     // fp32 symmetrized V, [z][pair][m]
__device__ float g_Vs2[NSP * 6 * EMB];
__device__ float g_C[3 * EMB];
__device__ float g_S1[NSP * 3];
__device__ float g_S2[NSP * 3];
__device__ float g_sb;
// pair-combined tables
__device__ __half g_Vc[NPAIR * 6 * EMB];   // 13.9 MB, fp16
__device__ float  g_Tc[NPAIR * EMB];       // 4.6 MB, fp32 (bias folded in)

// ---------------- precompute 1: scalar tables + U tables + C + S (merged) ----------------
__global__ void pre_tables(const float* __restrict__ W_rbf,
                           const float* __restrict__ b_rbf,
                           const float* __restrict__ W_scalar,
                           const float* __restrict__ b_scalar,
                           const float* __restrict__ emb,
                           const float* __restrict__ vemb,
                           const float* __restrict__ W_vector,
                           const float* __restrict__ b_vector,
                           const float* __restrict__ W_v2s) {
    __shared__ float sh[128];
    int m = threadIdx.x;
    int b = blockIdx.x;
    if (b < NRBF) {
        float s = 0.f;
        #pragma unroll 4
        for (int c = 0; c < EMB; c++)
            s = fmaf(W_rbf[b * EMB + c], W_scalar[(2 * EMB + c) * EMB + m], s);
        g_Wc[b * EMB + m] = s;
    } else if (b == NRBF) {
        float s = b_scalar[m];
        #pragma unroll 4
        for (int c = 0; c < EMB; c++)
            s = fmaf(b_rbf[c], W_scalar[(2 * EMB + c) * EMB + m], s);
        g_bias[m] = s;
    } else if (b < NRBF + 1 + NSP) {
        int z = b - NRBF - 1;
        float s1 = 0.f, s2 = 0.f;
        #pragma unroll 4
        for (int k = 0; k < EMB; k++) {
            float e = emb[z * EMB + k];
            s1 = fmaf(e, W_scalar[k * EMB + m], s1);
            s2 = fmaf(e, W_scalar[(EMB + k) * EMB + m], s2);
        }
        g_T1[z * EMB + m] = s1;
        g_T2[z * EMB + m] = s2;
    } else if (b < NRBF + 1 + NSP + NSP * 3) {
        int zz = b - (NRBF + 1 + NSP);
        int z = zz / 3, d = zz % 3;
        float u1 = 0.f, u2 = 0.f;
        #pragma unroll 4
        for (int k = 0; k < EMB; k++) {
            float v = vemb[(z * EMB + k) * 3 + d];
            u1 = fmaf(v, W_vector[k * EMB + m], u1);
            u2 = fmaf(v, W_vector[(EMB + k) * EMB + m], u2);
        }
        g_U1[(z * 3 + d) * EMB + m] = u1;
        g_U2[(z * 3 + d) * EMB + m] = u2;
        sh[m] = u1; __syncthreads();
        for (int s = 64; s > 0; s >>= 1) { if (m < s) sh[m] += sh[m + s]; __syncthreads(); }
        if (m == 0) g_S1[z * 3 + d] = sh[0];
        __syncthreads();
        sh[m] = u2; __syncthreads();
        for (int s = 64; s > 0; s >>= 1) { if (m < s) sh[m] += sh[m + s]; __syncthreads(); }
        if (m == 0) g_S2[z * 3 + d] = sh[0];
    } else {
        int dp = b - (NRBF + 1 + NSP + NSP * 3); // 0..2
        float s = 0.f;
        #pragma unroll 4
        for (int k = 0; k < EMB; k++)
            s = fmaf(b_vector[k], W_v2s[(k * 3 + dp) * EMB + m], s);
        g_C[dp * EMB + m] = s;
        if (dp == 0) {
            sh[m] = b_vector[m]; __syncthreads();
            for (int s2 = 64; s2 > 0; s2 >>= 1) { if (m < s2) sh[m] += sh[m + s2]; __syncthreads(); }
            if (m == 0) g_sb = sh[0];
        }
    }
}

// ---------------- precompute 2: symmetrized V (fp32, [z][pair][m]) ----------------
__global__ void pre_V(const float* __restrict__ W_v2s) {
    int m = threadIdx.x;
    int b = blockIdx.x;  // 0..569
    int p = b / NSP, z = b % NSP;
    const int PD[6]  = {0, 1, 2, 0, 0, 1};
    const int PDP[6] = {0, 1, 2, 1, 2, 2};
    int d = PD[p], dp = PDP[p];
    float v1 = 0.f, v2 = 0.f;
    #pragma unroll 4
    for (int k = 0; k < EMB; k++) {
        float w = W_v2s[(k * 3 + dp) * EMB + m];
        v1 = fmaf(g_U1[(z * 3 + d) * EMB + k], w, v1);
        v2 = fmaf(g_U2[(z * 3 + d) * EMB + k], w, v2);
    }
    if (d != dp) {
        #pragma unroll 4
        for (int k = 0; k < EMB; k++) {
            float w = W_v2s[(k * 3 + d) * EMB + m];
            v1 = fmaf(g_U1[(z * 3 + dp) * EMB + k], w, v1);
            v2 = fmaf(g_U2[(z * 3 + dp) * EMB + k], w, v2);
        }
    }
    g_Vs1[(z * 6 + p) * EMB + m] = v1;
    g_Vs2[(z * 6 + p) * EMB + m] = v2;
}

// ---------------- precompute 3: pair-combined tables ----------------
__global__ void pre_pair(void) {
    int m = threadIdx.x;          // 0..127
    int pair = blockIdx.x;        // 0..9024
    int zi = pair / NSP, zj = pair % NSP;
    g_Tc[pair * EMB + m] = g_T1[zi * EMB + m] + g_T2[zj * EMB + m] + g_bias[m];
    #pragma unroll
    for (int p = 0; p < 6; p++) {
        float v = g_Vs1[(zi * 6 + p) * EMB + m] + g_Vs2[(zj * 6 + p) * EMB + m];
        g_Vc[(pair * 6 + p) * EMB + m] = __float2half(v);
    }
}

// ---------------- main edge kernel ----------------
__global__ __launch_bounds__(256, 4)
void edge_kernel(const float* __restrict__ rbf,
                 const int* __restrict__ idnb_i,
                 const int* __restrict__ idnb_j,
                 const float* __restrict__ R,
                 const int* __restrict__ Z,
                 float* __restrict__ out,
                 int E) {
    __shared__ float s_Wc[NRBF * EMB];   // 8 KB
    __shared__ float s_C[3 * EMB];
    __shared__ float s_S1[NSP * 3];
    __shared__ float s_S2[NSP * 3];
    __shared__ float s_sb;

    for (int i = threadIdx.x; i < NRBF * EMB; i += 256) s_Wc[i] = g_Wc[i];
    for (int i = threadIdx.x; i < 3 * EMB; i += 256)    s_C[i] = g_C[i];
    for (int i = threadIdx.x; i < NSP * 3; i += 256) { s_S1[i] = g_S1[i]; s_S2[i] = g_S2[i]; }
    if (threadIdx.x == 0) s_sb = g_sb;
    __syncthreads();

    const int lane  = threadIdx.x & 31;
    const int warp  = blockIdx.x * (blockDim.x >> 5) + (threadIdx.x >> 5);
    const int nwarp = gridDim.x * (blockDim.x >> 5);
    const int ntiles = (E + EPW - 1) / EPW;
    const size_t o2 = (size_t)E * EMB;

    const float4* __restrict__ Tcf = reinterpret_cast<const float4*>(g_Tc);
    const uint2*  __restrict__ Vch = reinterpret_cast<const uint2*>(g_Vc);
    const float4* __restrict__ Wcf = reinterpret_cast<const float4*>(s_Wc);
    const float4* __restrict__ Cf  = reinterpret_cast<const float4*>(s_C);

    for (int t = warp; t < ntiles; t += nwarp) {
        int base = t * EPW;
        float4 acc[EPW];
        float bdx[EPW], bdy[EPW], bdz[EPW];
        int pr[EPW];
        float rv[EPW];

        // ---- per-edge meta: indices, bond dirs, rbf row, vector output ----
        #pragma unroll
        for (int e = 0; e < EPW; e++) {
            int edge = base + e;
            if (edge >= E) edge = E - 1;
            int i = idnb_i[edge];
            int j = idnb_j[edge];
            int zi = Z[i], zj = Z[j];
            pr[e] = zi * NSP + zj;
            float bx = R[j * 3 + 0] - R[i * 3 + 0];
            float by = R[j * 3 + 1] - R[i * 3 + 1];
            float bz = R[j * 3 + 2] - R[i * 3 + 2];
            float n = sqrtf(bx * bx + by * by + bz * bz) + 1e-8f;
            float inv = 1.0f / n;
            bdx[e] = bx * inv; bdy[e] = by * inv; bdz[e] = bz * inv;
            rv[e] = rbf[edge * NRBF + (lane & 15)];

            float sx = bdx[e] * (s_S1[zi * 3 + 0] + s_S2[zj * 3 + 0])
                     + bdy[e] * (s_S1[zi * 3 + 1] + s_S2[zj * 3 + 1])
                     + bdz[e] * (s_S1[zi * 3 + 2] + s_S2[zj * 3 + 2])
                     + s_sb;
            if (lane < 3) {
                float comp = (lane == 0) ? bdx[e] : (lane == 1) ? bdy[e] : bdz[e];
                out[o2 + (size_t)edge * 3 + lane] = comp * sx;
            }
        }

        // ---- acc init: combined species-pair table (bias folded in) ----
        #pragma unroll
        for (int e = 0; e < EPW; e++)
            acc[e] = Tcf[pr[e] * 32 + lane];

        // ---- rbf @ Wc, Wc row hoisted across edges ----
        #pragma unroll
        for (int r = 0; r < NRBF; r++) {
            float4 w = Wcf[r * 32 + lane];
            #pragma unroll
            for (int e = 0; e < EPW; e++) {
                float c = __shfl_sync(0xffffffffu, rv[e], r);
                acc[e].x = fmaf(c, w.x, acc[e].x);
                acc[e].y = fmaf(c, w.y, acc[e].y);
                acc[e].z = fmaf(c, w.z, acc[e].z);
                acc[e].w = fmaf(c, w.w, acc[e].w);
            }
        }

        // ---- bias-of-vector term ----
        {
            float4 c0 = Cf[lane], c1 = Cf[32 + lane], c2 = Cf[64 + lane];
            #pragma unroll
            for (int e = 0; e < EPW; e++) {
                acc[e].x += bdx[e] * c0.x + bdy[e] * c1.x + bdz[e] * c2.x;
                acc[e].y += bdx[e] * c0.y + bdy[e] * c1.y + bdz[e] * c2.y;
                acc[e].z += bdx[e] * c0.z + bdy[e] * c1.z + bdz[e] * c2.z;
                acc[e].w += bdx[e] * c0.w + bdy[e] * c1.w + bdz[e] * c2.w;
            }
        }

        // ---- quadratic-form pair loop: single combined fp16 gather ----
        const int PD[6]  = {0, 1, 2, 0, 0, 1};
        const int PDP[6] = {0, 1, 2, 1, 2, 2};
        #pragma unroll
        for (int p = 0; p < 6; p++) {
            const int d = PD[p], dp = PDP[p];
            #pragma unroll
            for (int e = 0; e < EPW; e++) {
                float b1 = (d  == 0) ? bdx[e] : (d  == 1) ? bdy[e] : bdz[e];
                float b2 = (dp == 0) ? bdx[e] : (dp == 1) ? bdy[e] : bdz[e];
                float c = b1 * b2;
                uint2 r1 = Vch[(pr[e] * 6 + p) * 32 + lane];
                float2 a0 = __half22float2(*reinterpret_cast<__half2*>(&r1.x));
                float2 a1 = __half22float2(*reinterpret_cast<__half2*>(&r1.y));
                acc[e].x = fmaf(c, a0.x, acc[e].x);
                acc[e].y = fmaf(c, a0.y, acc[e].y);
                acc[e].z = fmaf(c, a1.x, acc[e].z);
                acc[e].w = fmaf(c, a1.y, acc[e].w);
            }
        }

        // ---- store scalar block ----
        #pragma unroll
        for (int e = 0; e < EPW; e++) {
            int edge = base + e;
            if (edge >= E) edge = E - 1;
            reinterpret_cast<float4*>(out + (size_t)edge * EMB)[lane] = acc[e];
        }
    }
}

// ---------------- launcher ----------------
extern "C" void kernel_launch(void* const* d_in, const int* in_sizes, int n_in,
                              void* d_out, int out_size) {
    const int*   Z        = (const int*)d_in[0];
    const float* rbf      = (const float*)d_in[1];
    const int*   idnb_i   = (const int*)d_in[2];
    const int*   idnb_j   = (const int*)d_in[3];
    const float* R        = (const float*)d_in[4];
    const float* emb      = (const float*)d_in[5];
    const float* vemb     = (const float*)d_in[6];
    const float* W_rbf    = (const float*)d_in[7];
    const float* b_rbf    = (const float*)d_in[8];
    const float* W_scalar = (const float*)d_in[9];
    const float* b_scalar = (const float*)d_in[10];
    const float* W_vector = (const float*)d_in[11];
    const float* b_vector = (const float*)d_in[12];
    const float* W_v2s    = (const float*)d_in[13];
    int E = in_sizes[2];

    pre_tables<<<NRBF + 1 + NSP + NSP * 3 + 3, 128>>>(W_rbf, b_rbf, W_scalar, b_scalar,
                                                      emb, vemb, W_vector, b_vector, W_v2s);
    pre_V<<<6 * NSP, 128>>>(W_v2s);
    pre_pair<<<NPAIR, 128>>>();
    edge_kernel<<<2048, 256>>>(rbf, idnb_i, idnb_j, R, Z, (float*)d_out, E);
}